// round 3
// baseline (speedup 1.0000x reference)
#include <cuda_runtime.h>
#include <cstdint>

#define N_NODES 50000
#define N_EDGES 800000
#define DIM     64
#define N_REL   16

// ---------------- scratch (device globals: allocation-free) ----------------
__device__ float g_proj[(size_t)N_REL * N_NODES * DIM];  // 204.8 MB
__device__ float g_att[N_EDGES];

// sort-by-etype scratch
__device__ int g_cnt16[16];
__device__ int g_pos16[16];
__device__ int g_eidA[N_EDGES];   // edge ids grouped by relation

// sort-by-dst scratch (CSR)
__device__ int g_cntN[N_NODES];
__device__ int g_rowptr[N_NODES + 1];
__device__ int g_curN[N_NODES];
__device__ int g_eidB[N_EDGES];   // edge ids grouped by dst

// ---------------- helpers ----------------
__device__ __forceinline__ float fast_tanh(float x) {
    float xc = fminf(fmaxf(x, -15.f), 15.f);
    float t  = __expf(2.f * xc);
    return __fdividef(t - 1.f, t + 1.f);
}
__device__ __forceinline__ unsigned long long pack2(float x) {
    unsigned long long r;
    asm("mov.b64 %0, {%1, %1};" : "=l"(r) : "f"(x));
    return r;
}
__device__ __forceinline__ void ffma2(unsigned long long& d,
                                      unsigned long long a,
                                      unsigned long long b) {
    asm("fma.rn.f32x2 %0, %1, %2, %0;" : "+l"(d) : "l"(a), "l"(b));
}
__device__ __forceinline__ void unpack2(unsigned long long v, float& lo, float& hi) {
    asm("mov.b64 {%0, %1}, %2;" : "=f"(lo), "=f"(hi) : "l"(v));
}
__device__ __forceinline__ float leaky(float x) { return x >= 0.f ? x : 0.01f * x; }

// ---------------- sort machinery ----------------
__global__ void zero_counters_kernel() {
    int i = blockIdx.x * blockDim.x + threadIdx.x;
    if (i < N_NODES) g_cntN[i] = 0;
    if (i < 16)      g_cnt16[i] = 0;
}

__global__ void hist16_kernel(const int* __restrict__ etype) {
    __shared__ int lh[16];
    if (threadIdx.x < 16) lh[threadIdx.x] = 0;
    __syncthreads();
    for (int e = blockIdx.x * blockDim.x + threadIdx.x; e < N_EDGES;
         e += gridDim.x * blockDim.x)
        atomicAdd(&lh[etype[e]], 1);
    __syncthreads();
    if (threadIdx.x < 16) atomicAdd(&g_cnt16[threadIdx.x], lh[threadIdx.x]);
}

__global__ void scan16_kernel() {
    if (threadIdx.x == 0 && blockIdx.x == 0) {
        int off = 0;
        for (int t = 0; t < 16; t++) { g_pos16[t] = off; off += g_cnt16[t]; }
    }
}

__global__ void scatter16_kernel(const int* __restrict__ etype) {
    __shared__ int lh[16], lbase[16];
    int e = blockIdx.x * blockDim.x + threadIdx.x;
    if (threadIdx.x < 16) lh[threadIdx.x] = 0;
    __syncthreads();
    int t = 0, r = 0;
    bool valid = (e < N_EDGES);
    if (valid) { t = etype[e]; r = atomicAdd(&lh[t], 1); }
    __syncthreads();
    if (threadIdx.x < 16 && lh[threadIdx.x] > 0)
        lbase[threadIdx.x] = atomicAdd(&g_pos16[threadIdx.x], lh[threadIdx.x]);
    __syncthreads();
    if (valid) g_eidA[lbase[t] + r] = e;
}

__global__ void histN_kernel(const int* __restrict__ dst) {
    int e = blockIdx.x * blockDim.x + threadIdx.x;
    if (e < N_EDGES) atomicAdd(&g_cntN[dst[e]], 1);
}

__global__ void __launch_bounds__(1024) scanN_kernel() {
    const int PER = (N_NODES + 1023) / 1024;  // 49
    int tid  = threadIdx.x;
    int base = tid * PER;
    int sum = 0;
    for (int k = 0; k < PER; k++) {
        int i = base + k;
        if (i < N_NODES) sum += g_cntN[i];
    }
    int lane = tid & 31, wid = tid >> 5;
    int inc = sum;
    #pragma unroll
    for (int o = 1; o < 32; o <<= 1) {
        int v = __shfl_up_sync(0xffffffffu, inc, o);
        if (lane >= o) inc += v;
    }
    __shared__ int wsum[32];
    if (lane == 31) wsum[wid] = inc;
    __syncthreads();
    if (wid == 0) {
        int v = wsum[lane];
        #pragma unroll
        for (int o = 1; o < 32; o <<= 1) {
            int u = __shfl_up_sync(0xffffffffu, v, o);
            if (lane >= o) v += u;
        }
        wsum[lane] = v;
    }
    __syncthreads();
    int excl = inc - sum + (wid > 0 ? wsum[wid - 1] : 0);
    for (int k = 0; k < PER; k++) {
        int i = base + k;
        if (i < N_NODES) {
            g_rowptr[i] = excl;
            g_curN[i]   = excl;
            excl += g_cntN[i];
        }
    }
    if (tid == 1023) g_rowptr[N_NODES] = excl;
}

__global__ void scatterN_kernel(const int* __restrict__ dst) {
    int e = blockIdx.x * blockDim.x + threadIdx.x;
    if (e < N_EDGES) {
        int p = atomicAdd(&g_curN[dst[e]], 1);
        g_eidB[p] = e;
    }
}

// ---------------- K1: proj[r,n,:] = nfeat[n,:] @ W_r  (f32x2 packed FMA) ----
__global__ void __launch_bounds__(128) proj_kernel(const float* __restrict__ nfeat,
                                                   const float* __restrict__ relW) {
    __shared__ __align__(16) float Ws[64 * 64];
    __shared__ __align__(16) float Xs[64 * 128];

    const int r   = blockIdx.y;
    const int n0  = blockIdx.x * 128;
    const int tid = threadIdx.x;

    {
        const float4* wsrc = (const float4*)(relW + (size_t)r * 4096);
        float4* wdst = (float4*)Ws;
        #pragma unroll
        for (int i = tid; i < 1024; i += 128) wdst[i] = wsrc[i];
    }
    {
        int n = n0 + tid;
        if (n < N_NODES) {
            const float4* nr = (const float4*)(nfeat + (size_t)n * DIM);
            #pragma unroll
            for (int c4 = 0; c4 < 16; c4++) {
                float4 v = nr[c4];
                Xs[(c4 * 4 + 0) * 128 + tid] = v.x;
                Xs[(c4 * 4 + 1) * 128 + tid] = v.y;
                Xs[(c4 * 4 + 2) * 128 + tid] = v.z;
                Xs[(c4 * 4 + 3) * 128 + tid] = v.w;
            }
        } else {
            #pragma unroll
            for (int c = 0; c < 64; c++) Xs[c * 128 + tid] = 0.f;
        }
    }
    __syncthreads();

    const int cg = tid & 3;
    const int tr = tid >> 2;

    unsigned long long acc[4][8];
    #pragma unroll
    for (int m = 0; m < 4; m++)
        #pragma unroll
        for (int j = 0; j < 8; j++) acc[m][j] = 0ull;

    #pragma unroll 8
    for (int d = 0; d < 64; d++) {
        unsigned long long w2[8];
        const float* wrow = Ws + d * 64 + cg * 16;
        #pragma unroll
        for (int j = 0; j < 8; j++)
            w2[j] = *(const unsigned long long*)(wrow + 2 * j);
        #pragma unroll
        for (int m = 0; m < 4; m++) {
            unsigned long long x2 = pack2(Xs[d * 128 + tr * 4 + m]);
            #pragma unroll
            for (int j = 0; j < 8; j++) ffma2(acc[m][j], x2, w2[j]);
        }
    }

    #pragma unroll
    for (int m = 0; m < 4; m++) {
        int n = n0 + tr * 4 + m;
        if (n >= N_NODES) continue;
        float* orow = g_proj + ((size_t)r * N_NODES + n) * DIM + cg * 16;
        #pragma unroll
        for (int j = 0; j < 8; j++) {
            float lo, hi;
            unpack2(acc[m][j], lo, hi);
            orow[2 * j]     = lo;
            orow[2 * j + 1] = hi;
        }
    }
}

// ---------------- K2: per-edge attention logit (relation-sorted order) -----
__global__ void __launch_bounds__(256) att_kernel(const float* __restrict__ efeat,
                                                  const int* __restrict__ src,
                                                  const int* __restrict__ dst,
                                                  const int* __restrict__ etype) {
    int gw   = blockIdx.x * 8 + (threadIdx.x >> 5);   // sorted slot
    int lane = threadIdx.x & 31;
    if (gw >= N_EDGES) return;

    int e = g_eidA[gw];
    int s = src[e], d = dst[e], r = etype[e];
    const float2* t2 = (const float2*)(g_proj + ((size_t)r * N_NODES + s) * DIM);
    const float2* h2 = (const float2*)(g_proj + ((size_t)r * N_NODES + d) * DIM);
    const float2* e2 = (const float2*)(efeat + (size_t)e * DIM);

    float2 tv = t2[lane], hv = h2[lane], ev = e2[lane];
    float val = tv.x * fast_tanh(hv.x + ev.x) + tv.y * fast_tanh(hv.y + ev.y);

    #pragma unroll
    for (int off = 16; off; off >>= 1) val += __shfl_xor_sync(0xffffffffu, val, off);

    if (lane == 0) g_att[e] = val;
}

// ---------------- K3: fused edge-softmax + aggregation (warp per dst) ------
__global__ void __launch_bounds__(256) softagg_kernel(const float* __restrict__ nfeat,
                                                      const int* __restrict__ src,
                                                      float* __restrict__ hnb) {
    int d    = blockIdx.x * 8 + (threadIdx.x >> 5);
    int lane = threadIdx.x & 31;
    if (d >= N_NODES) return;

    int beg = g_rowptr[d], end = g_rowptr[d + 1];

    float m = -1e30f;
    for (int i = beg + lane; i < end; i += 32)
        m = fmaxf(m, g_att[g_eidB[i]]);
    #pragma unroll
    for (int o = 16; o; o >>= 1) m = fmaxf(m, __shfl_xor_sync(0xffffffffu, m, o));

    float s = 0.f;
    for (int i = beg + lane; i < end; i += 32)
        s += __expf(g_att[g_eidB[i]] - m);
    #pragma unroll
    for (int o = 16; o; o >>= 1) s += __shfl_xor_sync(0xffffffffu, s, o);

    float inv = (end > beg) ? (1.f / s) : 0.f;

    float2 acc = make_float2(0.f, 0.f);
    for (int i = beg; i < end; i++) {
        int   e = g_eidB[i];
        float a = __expf(g_att[e] - m) * inv;
        int  sn = src[e];
        float2 v = ((const float2*)(nfeat + (size_t)sn * DIM))[lane];
        acc.x += a * v.x;
        acc.y += a * v.y;
    }
    ((float2*)(hnb + (size_t)d * DIM))[lane] = acc;
}

// ---------------- K5: out (+)= leaky((nfeat OP hnb) @ W) ----------------
template <int MODE>
__global__ void __launch_bounds__(128) out_gemm_kernel(const float* __restrict__ nfeat,
                                                       const float* __restrict__ hnb,
                                                       const float* __restrict__ W,
                                                       float* __restrict__ out,
                                                       int accumulate) {
    __shared__ __align__(16) float Ws[64 * 64];
    __shared__ __align__(16) float Ss[64 * 64];

    const int n0  = blockIdx.x * 64;
    const int tid = threadIdx.x;

    {
        const float4* wsrc = (const float4*)W;
        float4* wdst = (float4*)Ws;
        #pragma unroll
        for (int i = tid; i < 1024; i += 128) wdst[i] = wsrc[i];
    }
    {
        int nn = tid & 63;
        int n  = n0 + nn;
        if (n < N_NODES) {
            const float4* a4 = (const float4*)(nfeat + (size_t)n * DIM);
            const float4* b4 = (const float4*)(hnb  + (size_t)n * DIM);
            for (int c4 = (tid >> 6); c4 < 16; c4 += 2) {
                float4 a = a4[c4], b = b4[c4];
                float4 sv;
                if (MODE == 0) sv = make_float4(a.x + b.x, a.y + b.y, a.z + b.z, a.w + b.w);
                else           sv = make_float4(a.x * b.x, a.y * b.y, a.z * b.z, a.w * b.w);
                Ss[(c4 * 4 + 0) * 64 + nn] = sv.x;
                Ss[(c4 * 4 + 1) * 64 + nn] = sv.y;
                Ss[(c4 * 4 + 2) * 64 + nn] = sv.z;
                Ss[(c4 * 4 + 3) * 64 + nn] = sv.w;
            }
        } else {
            for (int c4 = (tid >> 6); c4 < 16; c4 += 2) {
                Ss[(c4 * 4 + 0) * 64 + nn] = 0.f;
                Ss[(c4 * 4 + 1) * 64 + nn] = 0.f;
                Ss[(c4 * 4 + 2) * 64 + nn] = 0.f;
                Ss[(c4 * 4 + 3) * 64 + nn] = 0.f;
            }
        }
    }
    __syncthreads();

    const int cg = tid & 3;
    const int tr = tid >> 2;

    unsigned long long acc[2][8];
    #pragma unroll
    for (int m = 0; m < 2; m++)
        #pragma unroll
        for (int j = 0; j < 8; j++) acc[m][j] = 0ull;

    #pragma unroll 8
    for (int d = 0; d < 64; d++) {
        unsigned long long w2[8];
        const float* wrow = Ws + d * 64 + cg * 16;
        #pragma unroll
        for (int j = 0; j < 8; j++)
            w2[j] = *(const unsigned long long*)(wrow + 2 * j);
        #pragma unroll
        for (int m = 0; m < 2; m++) {
            unsigned long long x2 = pack2(Ss[d * 64 + tr * 2 + m]);
            #pragma unroll
            for (int j = 0; j < 8; j++) ffma2(acc[m][j], x2, w2[j]);
        }
    }

    #pragma unroll
    for (int m = 0; m < 2; m++) {
        int n = n0 + tr * 2 + m;
        if (n >= N_NODES) continue;
        float* orow = out + (size_t)n * DIM + cg * 16;
        #pragma unroll
        for (int j = 0; j < 8; j++) {
            float lo, hi;
            unpack2(acc[m][j], lo, hi);
            lo = leaky(lo);
            hi = leaky(hi);
            if (accumulate) { orow[2 * j] += lo; orow[2 * j + 1] += hi; }
            else            { orow[2 * j]  = lo; orow[2 * j + 1]  = hi; }
        }
    }
}

// ---------------- launch ----------------
extern "C" void kernel_launch(void* const* d_in, const int* in_sizes, int n_in,
                              void* d_out, int out_size) {
    const float* nfeat = (const float*)d_in[0];
    const float* efeat = (const float*)d_in[1];
    const float* relW  = (const float*)d_in[2];
    const float* W1    = (const float*)d_in[3];
    const float* W2    = (const float*)d_in[4];
    const int*   src   = (const int*)d_in[5];
    const int*   dst   = (const int*)d_in[6];
    const int*   etype = (const int*)d_in[7];

    float* hnb  = (float*)d_out;
    float* out2 = (float*)d_out + (size_t)N_NODES * DIM;

    const int EB = (N_EDGES + 255) / 256;   // 3125

    zero_counters_kernel<<<(N_NODES + 255) / 256, 256>>>();

    // sort by etype (for att L2 locality)
    hist16_kernel<<<512, 256>>>(etype);
    scan16_kernel<<<1, 32>>>();
    scatter16_kernel<<<EB, 256>>>(etype);

    // sort by dst (CSR for atomic-free softmax+agg)
    histN_kernel<<<EB, 256>>>(dst);
    scanN_kernel<<<1, 1024>>>();
    scatterN_kernel<<<EB, 256>>>(dst);

    // projection GEMMs
    dim3 g1((N_NODES + 127) / 128, N_REL);
    proj_kernel<<<g1, 128>>>(nfeat, relW);

    // attention logits in relation-sorted order
    att_kernel<<<(N_EDGES + 7) / 8, 256>>>(efeat, src, dst, etype);

    // fused edge-softmax + aggregation, warp per dst
    softagg_kernel<<<(N_NODES + 7) / 8, 256>>>(nfeat, src, hnb);

    // bi-interaction epilogue
    out_gemm_kernel<0><<<(N_NODES + 63) / 64, 128>>>(nfeat, hnb, W1, out2, 0);
    out_gemm_kernel<1><<<(N_NODES + 63) / 64, 128>>>(nfeat, hnb, W2, out2, 1);
}

// round 4
// speedup vs baseline: 1.1549x; 1.1549x over previous
#include <cuda_runtime.h>
#include <cstdint>

#define N_NODES 50000
#define N_EDGES 800000
#define DIM     64
#define N_REL   16

// ---------------- scratch (device globals: allocation-free) ----------------
__device__ float g_proj[(size_t)N_REL * N_NODES * DIM];  // 204.8 MB
__device__ float g_att[N_EDGES];                          // exp(att)
__device__ float g_denom[N_NODES];

// ---------------- helpers ----------------
__device__ __forceinline__ float fast_tanh(float x) {
    float xc = fminf(fmaxf(x, -15.f), 15.f);
    float t  = __expf(2.f * xc);
    return __fdividef(t - 1.f, t + 1.f);
}
__device__ __forceinline__ unsigned long long pack2(float x) {
    unsigned long long r;
    asm("mov.b64 %0, {%1, %1};" : "=l"(r) : "f"(x));
    return r;
}
__device__ __forceinline__ void ffma2(unsigned long long& d,
                                      unsigned long long a,
                                      unsigned long long b) {
    asm("fma.rn.f32x2 %0, %1, %2, %0;" : "+l"(d) : "l"(a), "l"(b));
}
__device__ __forceinline__ void unpack2(unsigned long long v, float& lo, float& hi) {
    asm("mov.b64 {%0, %1}, %2;" : "=f"(lo), "=f"(hi) : "l"(v));
}
__device__ __forceinline__ float leaky(float x) { return x >= 0.f ? x : 0.01f * x; }

// ---------------- launch #1: zero h_neighbor ----------------
__global__ void init_hnb_kernel(float* __restrict__ hnb) {
    int i = blockIdx.x * blockDim.x + threadIdx.x;
    if (i < N_NODES * DIM / 4) ((float4*)hnb)[i] = make_float4(0.f, 0.f, 0.f, 0.f);
}

// ---------------- launch #3: zero denom ----------------
__global__ void init_denom_kernel() {
    int i = blockIdx.x * blockDim.x + threadIdx.x;
    if (i < N_NODES) g_denom[i] = 0.f;
}

// ---------------- launch #2: proj[r,n,:] = nfeat[n,:] @ W_r ----------------
// Block: 128 threads, tile = 192 nodes of one relation.
// Thread (cg = tid&3, tr = tid>>2): nodes tr*6..tr*6+5, cols cg*16..cg*16+15.
// Per d-step: 8 LDS.64 (W) + 6 LDS.32 (X) feed 48 FFMA2 -> FMA-issue-bound.
#define PROJ_TN 192
__global__ void __launch_bounds__(128) proj_kernel(const float* __restrict__ nfeat,
                                                   const float* __restrict__ relW) {
    __shared__ __align__(16) float Ws[64 * 64];          // 16 KB [d][e]
    __shared__ __align__(16) float Xs[64 * PROJ_TN];     // 48 KB transposed [d][node]

    const int r   = blockIdx.y;
    const int n0  = blockIdx.x * PROJ_TN;
    const int tid = threadIdx.x;

    {
        const float4* wsrc = (const float4*)(relW + (size_t)r * 4096);
        float4* wdst = (float4*)Ws;
        #pragma unroll
        for (int i = tid; i < 1024; i += 128) wdst[i] = wsrc[i];
    }
    #pragma unroll
    for (int k = 0; k < 2; k++) {
        int nn = tid + k * 128;
        if (nn >= PROJ_TN) break;
        int n = n0 + nn;
        if (n < N_NODES) {
            const float4* nr = (const float4*)(nfeat + (size_t)n * DIM);
            #pragma unroll
            for (int c4 = 0; c4 < 16; c4++) {
                float4 v = nr[c4];
                Xs[(c4 * 4 + 0) * PROJ_TN + nn] = v.x;
                Xs[(c4 * 4 + 1) * PROJ_TN + nn] = v.y;
                Xs[(c4 * 4 + 2) * PROJ_TN + nn] = v.z;
                Xs[(c4 * 4 + 3) * PROJ_TN + nn] = v.w;
            }
        } else {
            #pragma unroll
            for (int c = 0; c < 64; c++) Xs[c * PROJ_TN + nn] = 0.f;
        }
    }
    __syncthreads();

    const int cg = tid & 3;
    const int tr = tid >> 2;

    unsigned long long acc[6][8];
    #pragma unroll
    for (int m = 0; m < 6; m++)
        #pragma unroll
        for (int j = 0; j < 8; j++) acc[m][j] = 0ull;

    #pragma unroll 4
    for (int d = 0; d < 64; d++) {
        unsigned long long w2[8];
        const float* wrow = Ws + d * 64 + cg * 16;
        #pragma unroll
        for (int j = 0; j < 8; j++)
            w2[j] = *(const unsigned long long*)(wrow + 2 * j);
        #pragma unroll
        for (int m = 0; m < 6; m++) {
            unsigned long long x2 = pack2(Xs[d * PROJ_TN + tr * 6 + m]);
            #pragma unroll
            for (int j = 0; j < 8; j++) ffma2(acc[m][j], x2, w2[j]);
        }
    }

    #pragma unroll
    for (int m = 0; m < 6; m++) {
        int n = n0 + tr * 6 + m;
        if (n >= N_NODES) continue;
        float* orow = g_proj + ((size_t)r * N_NODES + n) * DIM + cg * 16;
        #pragma unroll
        for (int j = 0; j < 8; j++) {
            float lo, hi;
            unpack2(acc[m][j], lo, hi);
            orow[2 * j]     = lo;
            orow[2 * j + 1] = hi;
        }
    }
}

// ---------------- launch #4: att logit + exp + denom (fused softmax) -------
__global__ void __launch_bounds__(256) att_kernel(const float* __restrict__ efeat,
                                                  const int* __restrict__ src,
                                                  const int* __restrict__ dst,
                                                  const int* __restrict__ etype) {
    int gt   = blockIdx.x * blockDim.x + threadIdx.x;
    int e    = gt >> 5;
    int lane = threadIdx.x & 31;
    if (e >= N_EDGES) return;

    int s = src[e], d = dst[e], r = etype[e];
    const float2* t2 = (const float2*)(g_proj + ((size_t)r * N_NODES + s) * DIM);
    const float2* h2 = (const float2*)(g_proj + ((size_t)r * N_NODES + d) * DIM);
    const float2* e2 = (const float2*)(efeat + (size_t)e * DIM);

    float2 tv = t2[lane], hv = h2[lane], ev = e2[lane];
    float val = tv.x * fast_tanh(hv.x + ev.x) + tv.y * fast_tanh(hv.y + ev.y);

    #pragma unroll
    for (int off = 16; off; off >>= 1) val += __shfl_xor_sync(0xffffffffu, val, off);

    if (lane == 0) {
        // no max-subtraction: |att| <~ 30 << 88, softmax shift-invariant
        float ex = __expf(val);
        g_att[e] = ex;
        atomicAdd(&g_denom[d], ex);
    }
}

// ---------------- launch #5: h_neighbor[dst] += a * nfeat[src] -------------
__global__ void __launch_bounds__(256) agg_kernel(const float* __restrict__ nfeat,
                                                  const int* __restrict__ src,
                                                  const int* __restrict__ dst,
                                                  float* __restrict__ hnb) {
    int gt = blockIdx.x * blockDim.x + threadIdx.x;
    int e  = gt >> 4;                 // 16 lanes per edge
    int sl = threadIdx.x & 15;
    if (e >= N_EDGES) return;

    int s = src[e], d = dst[e];
    float a = g_att[e] / g_denom[d];

    float4 v = ((const float4*)(nfeat + (size_t)s * DIM))[sl];
    float4 w = make_float4(v.x * a, v.y * a, v.z * a, v.w * a);
    float4* p = ((float4*)(hnb + (size_t)d * DIM)) + sl;
    atomicAdd(p, w);
}

// ---------------- launches #6/#7: out (+)= leaky((nfeat OP hnb) @ W) -------
template <int MODE>
__global__ void __launch_bounds__(128) out_gemm_kernel(const float* __restrict__ nfeat,
                                                       const float* __restrict__ hnb,
                                                       const float* __restrict__ W,
                                                       float* __restrict__ out,
                                                       int accumulate) {
    __shared__ __align__(16) float Ws[64 * 64];
    __shared__ __align__(16) float Ss[64 * 64];

    const int n0  = blockIdx.x * 64;
    const int tid = threadIdx.x;

    {
        const float4* wsrc = (const float4*)W;
        float4* wdst = (float4*)Ws;
        #pragma unroll
        for (int i = tid; i < 1024; i += 128) wdst[i] = wsrc[i];
    }
    {
        int nn = tid & 63;
        int n  = n0 + nn;
        if (n < N_NODES) {
            const float4* a4 = (const float4*)(nfeat + (size_t)n * DIM);
            const float4* b4 = (const float4*)(hnb  + (size_t)n * DIM);
            for (int c4 = (tid >> 6); c4 < 16; c4 += 2) {
                float4 a = a4[c4], b = b4[c4];
                float4 sv;
                if (MODE == 0) sv = make_float4(a.x + b.x, a.y + b.y, a.z + b.z, a.w + b.w);
                else           sv = make_float4(a.x * b.x, a.y * b.y, a.z * b.z, a.w * b.w);
                Ss[(c4 * 4 + 0) * 64 + nn] = sv.x;
                Ss[(c4 * 4 + 1) * 64 + nn] = sv.y;
                Ss[(c4 * 4 + 2) * 64 + nn] = sv.z;
                Ss[(c4 * 4 + 3) * 64 + nn] = sv.w;
            }
        } else {
            for (int c4 = (tid >> 6); c4 < 16; c4 += 2) {
                Ss[(c4 * 4 + 0) * 64 + nn] = 0.f;
                Ss[(c4 * 4 + 1) * 64 + nn] = 0.f;
                Ss[(c4 * 4 + 2) * 64 + nn] = 0.f;
                Ss[(c4 * 4 + 3) * 64 + nn] = 0.f;
            }
        }
    }
    __syncthreads();

    const int cg = tid & 3;
    const int tr = tid >> 2;

    unsigned long long acc[2][8];
    #pragma unroll
    for (int m = 0; m < 2; m++)
        #pragma unroll
        for (int j = 0; j < 8; j++) acc[m][j] = 0ull;

    #pragma unroll 8
    for (int d = 0; d < 64; d++) {
        unsigned long long w2[8];
        const float* wrow = Ws + d * 64 + cg * 16;
        #pragma unroll
        for (int j = 0; j < 8; j++)
            w2[j] = *(const unsigned long long*)(wrow + 2 * j);
        #pragma unroll
        for (int m = 0; m < 2; m++) {
            unsigned long long x2 = pack2(Ss[d * 64 + tr * 2 + m]);
            #pragma unroll
            for (int j = 0; j < 8; j++) ffma2(acc[m][j], x2, w2[j]);
        }
    }

    #pragma unroll
    for (int m = 0; m < 2; m++) {
        int n = n0 + tr * 2 + m;
        if (n >= N_NODES) continue;
        float* orow = out + (size_t)n * DIM + cg * 16;
        #pragma unroll
        for (int j = 0; j < 8; j++) {
            float lo, hi;
            unpack2(acc[m][j], lo, hi);
            lo = leaky(lo);
            hi = leaky(hi);
            if (accumulate) { orow[2 * j] += lo; orow[2 * j + 1] += hi; }
            else            { orow[2 * j]  = lo; orow[2 * j + 1]  = hi; }
        }
    }
}

// ---------------- launch ----------------
extern "C" void kernel_launch(void* const* d_in, const int* in_sizes, int n_in,
                              void* d_out, int out_size) {
    const float* nfeat = (const float*)d_in[0];
    const float* efeat = (const float*)d_in[1];
    const float* relW  = (const float*)d_in[2];
    const float* W1    = (const float*)d_in[3];
    const float* W2    = (const float*)d_in[4];
    const int*   src   = (const int*)d_in[5];
    const int*   dst   = (const int*)d_in[6];
    const int*   etype = (const int*)d_in[7];

    float* hnb  = (float*)d_out;
    float* out2 = (float*)d_out + (size_t)N_NODES * DIM;

    // #1
    init_hnb_kernel<<<(N_NODES * DIM / 4 + 255) / 256, 256>>>(hnb);
    // #2
    dim3 g1((N_NODES + PROJ_TN - 1) / PROJ_TN, N_REL);
    proj_kernel<<<g1, 128>>>(nfeat, relW);
    // #3
    init_denom_kernel<<<(N_NODES + 255) / 256, 256>>>();
    // #4  <- ncu profiles this launch
    att_kernel<<<(N_EDGES * 32 + 255) / 256, 256>>>(efeat, src, dst, etype);
    // #5
    agg_kernel<<<(N_EDGES * 16 + 255) / 256, 256>>>(nfeat, src, dst, hnb);
    // #6, #7
    out_gemm_kernel<0><<<(N_NODES + 63) / 64, 128>>>(nfeat, hnb, W1, out2, 0);
    out_gemm_kernel<1><<<(N_NODES + 63) / 64, 128>>>(nfeat, hnb, W2, out2, 1);
}

// round 5
// speedup vs baseline: 1.2445x; 1.0776x over previous
#include <cuda_runtime.h>
#include <cstdint>

#define N_NODES 50000
#define N_EDGES 800000
#define DIM     64
#define N_REL   16

// ---------------- scratch (device globals: allocation-free) ----------------
__device__ float g_proj[(size_t)N_REL * N_NODES * DIM];  // 204.8 MB
__device__ float g_denom[N_NODES];

// ---------------- helpers ----------------
__device__ __forceinline__ float fast_tanh(float x) {
    float xc = fminf(fmaxf(x, -15.f), 15.f);
    float t  = __expf(2.f * xc);
    return __fdividef(t - 1.f, t + 1.f);
}
__device__ __forceinline__ unsigned long long pack2(float x) {
    unsigned long long r;
    asm("mov.b64 %0, {%1, %1};" : "=l"(r) : "f"(x));
    return r;
}
__device__ __forceinline__ void ffma2(unsigned long long& d,
                                      unsigned long long a,
                                      unsigned long long b) {
    asm("fma.rn.f32x2 %0, %1, %2, %0;" : "+l"(d) : "l"(a), "l"(b));
}
__device__ __forceinline__ void unpack2(unsigned long long v, float& lo, float& hi) {
    asm("mov.b64 {%0, %1}, %2;" : "=f"(lo), "=f"(hi) : "l"(v));
}
__device__ __forceinline__ float leaky(float x) { return x >= 0.f ? x : 0.01f * x; }

// ---------------- launch #1: zero h_neighbor accumulator ----------------
__global__ void init_hnb_kernel(float* __restrict__ hnb) {
    int i = blockIdx.x * blockDim.x + threadIdx.x;
    if (i < N_NODES * DIM / 4) ((float4*)hnb)[i] = make_float4(0.f, 0.f, 0.f, 0.f);
}

// ---------------- launch #3: zero denom ----------------
__global__ void init_denom_kernel() {
    int i = blockIdx.x * blockDim.x + threadIdx.x;
    if (i < N_NODES) g_denom[i] = 0.f;
}

// ---------------- launch #2: proj[r,n,:] = nfeat[n,:] @ W_r ----------------
#define PROJ_TN 192
__global__ void __launch_bounds__(128) proj_kernel(const float* __restrict__ nfeat,
                                                   const float* __restrict__ relW) {
    __shared__ __align__(16) float Ws[64 * 64];          // 16 KB [d][e]
    __shared__ __align__(16) float Xs[64 * PROJ_TN];     // 48 KB transposed [d][node]

    const int r   = blockIdx.y;
    const int n0  = blockIdx.x * PROJ_TN;
    const int tid = threadIdx.x;

    {
        const float4* wsrc = (const float4*)(relW + (size_t)r * 4096);
        float4* wdst = (float4*)Ws;
        #pragma unroll
        for (int i = tid; i < 1024; i += 128) wdst[i] = wsrc[i];
    }
    #pragma unroll
    for (int k = 0; k < 2; k++) {
        int nn = tid + k * 128;
        if (nn >= PROJ_TN) break;
        int n = n0 + nn;
        if (n < N_NODES) {
            const float4* nr = (const float4*)(nfeat + (size_t)n * DIM);
            #pragma unroll
            for (int c4 = 0; c4 < 16; c4++) {
                float4 v = nr[c4];
                Xs[(c4 * 4 + 0) * PROJ_TN + nn] = v.x;
                Xs[(c4 * 4 + 1) * PROJ_TN + nn] = v.y;
                Xs[(c4 * 4 + 2) * PROJ_TN + nn] = v.z;
                Xs[(c4 * 4 + 3) * PROJ_TN + nn] = v.w;
            }
        } else {
            #pragma unroll
            for (int c = 0; c < 64; c++) Xs[c * PROJ_TN + nn] = 0.f;
        }
    }
    __syncthreads();

    const int cg = tid & 3;
    const int tr = tid >> 2;

    unsigned long long acc[6][8];
    #pragma unroll
    for (int m = 0; m < 6; m++)
        #pragma unroll
        for (int j = 0; j < 8; j++) acc[m][j] = 0ull;

    #pragma unroll 4
    for (int d = 0; d < 64; d++) {
        unsigned long long w2[8];
        const float* wrow = Ws + d * 64 + cg * 16;
        #pragma unroll
        for (int j = 0; j < 8; j++)
            w2[j] = *(const unsigned long long*)(wrow + 2 * j);
        #pragma unroll
        for (int m = 0; m < 6; m++) {
            unsigned long long x2 = pack2(Xs[d * PROJ_TN + tr * 6 + m]);
            #pragma unroll
            for (int j = 0; j < 8; j++) ffma2(acc[m][j], x2, w2[j]);
        }
    }

    #pragma unroll
    for (int m = 0; m < 6; m++) {
        int n = n0 + tr * 6 + m;
        if (n >= N_NODES) continue;
        float* orow = g_proj + ((size_t)r * N_NODES + n) * DIM + cg * 16;
        #pragma unroll
        for (int j = 0; j < 8; j++) {
            float lo, hi;
            unpack2(acc[m][j], lo, hi);
            orow[2 * j]     = lo;
            orow[2 * j + 1] = hi;
        }
    }
}

// ---------------- launch #4: FUSED att + softmax-numerator aggregation -----
// Per warp: one edge. Logit -> exp (unshifted; |att| << 88) -> atomically
// accumulate denom[d] += ex and hnb[d] += ex * nfeat[s]. Normalization is
// deferred to the normalize kernel.
__global__ void __launch_bounds__(256) att_fused_kernel(const float* __restrict__ efeat,
                                                        const float* __restrict__ nfeat,
                                                        const int* __restrict__ src,
                                                        const int* __restrict__ dst,
                                                        const int* __restrict__ etype,
                                                        float* __restrict__ hnb) {
    int gt   = blockIdx.x * blockDim.x + threadIdx.x;
    int e    = gt >> 5;
    int lane = threadIdx.x & 31;
    if (e >= N_EDGES) return;

    int s = src[e], d = dst[e], r = etype[e];
    const float2* t2 = (const float2*)(g_proj + ((size_t)r * N_NODES + s) * DIM);
    const float2* h2 = (const float2*)(g_proj + ((size_t)r * N_NODES + d) * DIM);
    const float2* e2 = (const float2*)(efeat + (size_t)e * DIM);

    float2 tv = t2[lane], hv = h2[lane];
    float2 ev = __ldcs(&e2[lane]);   // streaming: don't pollute L2 (keep proj rows)
    float val = tv.x * fast_tanh(hv.x + ev.x) + tv.y * fast_tanh(hv.y + ev.y);

    #pragma unroll
    for (int off = 16; off; off >>= 1) val += __shfl_xor_sync(0xffffffffu, val, off);

    float ex = __expf(val);          // available in all lanes (butterfly reduce)

    if (lane == 0) atomicAdd(&g_denom[d], ex);
    if (lane < 16) {
        float4 v = ((const float4*)(nfeat + (size_t)s * DIM))[lane];
        float4 w = make_float4(ex * v.x, ex * v.y, ex * v.z, ex * v.w);
        atomicAdd(((float4*)(hnb + (size_t)d * DIM)) + lane, w);
    }
}

// ---------------- launch #5: normalize hnb by denom ----------------
__global__ void normalize_kernel(float* __restrict__ hnb) {
    int i = blockIdx.x * blockDim.x + threadIdx.x;   // float4 index
    if (i >= N_NODES * DIM / 4) return;
    int n = i >> 4;
    float den = g_denom[n];
    float inv = (den > 0.f) ? (1.f / den) : 0.f;     // empty segment -> 0
    float4 v = ((float4*)hnb)[i];
    ((float4*)hnb)[i] = make_float4(v.x * inv, v.y * inv, v.z * inv, v.w * inv);
}

// ---------------- launches #6/#7: out (+)= leaky((nfeat OP hnb) @ W) -------
template <int MODE>
__global__ void __launch_bounds__(128) out_gemm_kernel(const float* __restrict__ nfeat,
                                                       const float* __restrict__ hnb,
                                                       const float* __restrict__ W,
                                                       float* __restrict__ out,
                                                       int accumulate) {
    __shared__ __align__(16) float Ws[64 * 64];
    __shared__ __align__(16) float Ss[64 * 64];

    const int n0  = blockIdx.x * 64;
    const int tid = threadIdx.x;

    {
        const float4* wsrc = (const float4*)W;
        float4* wdst = (float4*)Ws;
        #pragma unroll
        for (int i = tid; i < 1024; i += 128) wdst[i] = wsrc[i];
    }
    {
        int nn = tid & 63;
        int n  = n0 + nn;
        if (n < N_NODES) {
            const float4* a4 = (const float4*)(nfeat + (size_t)n * DIM);
            const float4* b4 = (const float4*)(hnb  + (size_t)n * DIM);
            for (int c4 = (tid >> 6); c4 < 16; c4 += 2) {
                float4 a = a4[c4], b = b4[c4];
                float4 sv;
                if (MODE == 0) sv = make_float4(a.x + b.x, a.y + b.y, a.z + b.z, a.w + b.w);
                else           sv = make_float4(a.x * b.x, a.y * b.y, a.z * b.z, a.w * b.w);
                Ss[(c4 * 4 + 0) * 64 + nn] = sv.x;
                Ss[(c4 * 4 + 1) * 64 + nn] = sv.y;
                Ss[(c4 * 4 + 2) * 64 + nn] = sv.z;
                Ss[(c4 * 4 + 3) * 64 + nn] = sv.w;
            }
        } else {
            for (int c4 = (tid >> 6); c4 < 16; c4 += 2) {
                Ss[(c4 * 4 + 0) * 64 + nn] = 0.f;
                Ss[(c4 * 4 + 1) * 64 + nn] = 0.f;
                Ss[(c4 * 4 + 2) * 64 + nn] = 0.f;
                Ss[(c4 * 4 + 3) * 64 + nn] = 0.f;
            }
        }
    }
    __syncthreads();

    const int cg = tid & 3;
    const int tr = tid >> 2;

    unsigned long long acc[2][8];
    #pragma unroll
    for (int m = 0; m < 2; m++)
        #pragma unroll
        for (int j = 0; j < 8; j++) acc[m][j] = 0ull;

    #pragma unroll 8
    for (int d = 0; d < 64; d++) {
        unsigned long long w2[8];
        const float* wrow = Ws + d * 64 + cg * 16;
        #pragma unroll
        for (int j = 0; j < 8; j++)
            w2[j] = *(const unsigned long long*)(wrow + 2 * j);
        #pragma unroll
        for (int m = 0; m < 2; m++) {
            unsigned long long x2 = pack2(Ss[d * 64 + tr * 2 + m]);
            #pragma unroll
            for (int j = 0; j < 8; j++) ffma2(acc[m][j], x2, w2[j]);
        }
    }

    #pragma unroll
    for (int m = 0; m < 2; m++) {
        int n = n0 + tr * 2 + m;
        if (n >= N_NODES) continue;
        float* orow = out + (size_t)n * DIM + cg * 16;
        #pragma unroll
        for (int j = 0; j < 8; j++) {
            float lo, hi;
            unpack2(acc[m][j], lo, hi);
            lo = leaky(lo);
            hi = leaky(hi);
            if (accumulate) { orow[2 * j] += lo; orow[2 * j + 1] += hi; }
            else            { orow[2 * j]  = lo; orow[2 * j + 1]  = hi; }
        }
    }
}

// ---------------- launch ----------------
extern "C" void kernel_launch(void* const* d_in, const int* in_sizes, int n_in,
                              void* d_out, int out_size) {
    const float* nfeat = (const float*)d_in[0];
    const float* efeat = (const float*)d_in[1];
    const float* relW  = (const float*)d_in[2];
    const float* W1    = (const float*)d_in[3];
    const float* W2    = (const float*)d_in[4];
    const int*   src   = (const int*)d_in[5];
    const int*   dst   = (const int*)d_in[6];
    const int*   etype = (const int*)d_in[7];

    float* hnb  = (float*)d_out;
    float* out2 = (float*)d_out + (size_t)N_NODES * DIM;

    // #1
    init_hnb_kernel<<<(N_NODES * DIM / 4 + 255) / 256, 256>>>(hnb);
    // #2
    dim3 g1((N_NODES + PROJ_TN - 1) / PROJ_TN, N_REL);
    proj_kernel<<<g1, 128>>>(nfeat, relW);
    // #3
    init_denom_kernel<<<(N_NODES + 255) / 256, 256>>>();
    // #4  <- ncu profiles this launch
    att_fused_kernel<<<(N_EDGES * 32 + 255) / 256, 256>>>(efeat, nfeat, src, dst, etype, hnb);
    // #5
    normalize_kernel<<<(N_NODES * DIM / 4 + 255) / 256, 256>>>(hnb);
    // #6, #7
    out_gemm_kernel<0><<<(N_NODES + 63) / 64, 128>>>(nfeat, hnb, W1, out2, 0);
    out_gemm_kernel<1><<<(N_NODES + 63) / 64, 128>>>(nfeat, hnb, W2, out2, 1);
}

// round 6
// speedup vs baseline: 1.3584x; 1.0915x over previous
#include <cuda_runtime.h>
#include <cstdint>

#define N_NODES 50000
#define N_EDGES 800000
#define DIM     64
#define N_REL   16

// ---------------- scratch (device globals: allocation-free) ----------------
__device__ float g_proj[(size_t)N_REL * N_NODES * DIM];  // 204.8 MB
__device__ float g_denom[N_NODES];

// ---------------- helpers ----------------
__device__ __forceinline__ float fast_tanh(float x) {
    float xc = fminf(fmaxf(x, -15.f), 15.f);
    float t  = __expf(2.f * xc);
    return __fdividef(t - 1.f, t + 1.f);
}
__device__ __forceinline__ unsigned long long pack2(float x) {
    unsigned long long r;
    asm("mov.b64 %0, {%1, %1};" : "=l"(r) : "f"(x));
    return r;
}
__device__ __forceinline__ void ffma2(unsigned long long& d,
                                      unsigned long long a,
                                      unsigned long long b) {
    asm("fma.rn.f32x2 %0, %1, %2, %0;" : "+l"(d) : "l"(a), "l"(b));
}
__device__ __forceinline__ void unpack2(unsigned long long v, float& lo, float& hi) {
    asm("mov.b64 {%0, %1}, %2;" : "=f"(lo), "=f"(hi) : "l"(v));
}
__device__ __forceinline__ float leaky(float x) { return x >= 0.f ? x : 0.01f * x; }

// ---------------- launch #1: zero h_neighbor accumulator ----------------
__global__ void init_hnb_kernel(float* __restrict__ hnb) {
    int i = blockIdx.x * blockDim.x + threadIdx.x;
    if (i < N_NODES * DIM / 4) ((float4*)hnb)[i] = make_float4(0.f, 0.f, 0.f, 0.f);
}

// ---------------- launch #2: zero denom ----------------
__global__ void init_denom_kernel() {
    int i = blockIdx.x * blockDim.x + threadIdx.x;
    if (i < N_NODES) g_denom[i] = 0.f;
}

// ---------------- launches #3/#4: proj[r,n,:] = nfeat[n,:] @ W_r -----------
// (split into two relation halves so ncu's slot-#4 capture measures proj)
#define PROJ_TN 192
__global__ void __launch_bounds__(128) proj_kernel(const float* __restrict__ nfeat,
                                                   const float* __restrict__ relW,
                                                   int r_base) {
    __shared__ __align__(16) float Ws[64 * 64];          // 16 KB [d][e]
    __shared__ __align__(16) float Xs[64 * PROJ_TN];     // 48 KB transposed [d][node]

    const int r   = r_base + blockIdx.y;
    const int n0  = blockIdx.x * PROJ_TN;
    const int tid = threadIdx.x;

    {
        const float4* wsrc = (const float4*)(relW + (size_t)r * 4096);
        float4* wdst = (float4*)Ws;
        #pragma unroll
        for (int i = tid; i < 1024; i += 128) wdst[i] = wsrc[i];
    }
    #pragma unroll
    for (int k = 0; k < 2; k++) {
        int nn = tid + k * 128;
        if (nn >= PROJ_TN) break;
        int n = n0 + nn;
        if (n < N_NODES) {
            const float4* nr = (const float4*)(nfeat + (size_t)n * DIM);
            #pragma unroll
            for (int c4 = 0; c4 < 16; c4++) {
                float4 v = nr[c4];
                Xs[(c4 * 4 + 0) * PROJ_TN + nn] = v.x;
                Xs[(c4 * 4 + 1) * PROJ_TN + nn] = v.y;
                Xs[(c4 * 4 + 2) * PROJ_TN + nn] = v.z;
                Xs[(c4 * 4 + 3) * PROJ_TN + nn] = v.w;
            }
        } else {
            #pragma unroll
            for (int c = 0; c < 64; c++) Xs[c * PROJ_TN + nn] = 0.f;
        }
    }
    __syncthreads();

    const int cg = tid & 3;
    const int tr = tid >> 2;

    unsigned long long acc[6][8];
    #pragma unroll
    for (int m = 0; m < 6; m++)
        #pragma unroll
        for (int j = 0; j < 8; j++) acc[m][j] = 0ull;

    #pragma unroll 4
    for (int d = 0; d < 64; d++) {
        unsigned long long w2[8];
        const float* wrow = Ws + d * 64 + cg * 16;
        #pragma unroll
        for (int j = 0; j < 8; j++)
            w2[j] = *(const unsigned long long*)(wrow + 2 * j);
        #pragma unroll
        for (int m = 0; m < 6; m++) {
            unsigned long long x2 = pack2(Xs[d * PROJ_TN + tr * 6 + m]);
            #pragma unroll
            for (int j = 0; j < 8; j++) ffma2(acc[m][j], x2, w2[j]);
        }
    }

    #pragma unroll
    for (int m = 0; m < 6; m++) {
        int n = n0 + tr * 6 + m;
        if (n >= N_NODES) continue;
        float* orow = g_proj + ((size_t)r * N_NODES + n) * DIM + cg * 16;
        #pragma unroll
        for (int j = 0; j < 8; j++) {
            float lo, hi;
            unpack2(acc[m][j], lo, hi);
            orow[2 * j]     = lo;
            orow[2 * j + 1] = hi;
        }
    }
}

// ---------------- launch #5: FUSED att + softmax-numerator aggregation -----
// Half-warp (16 lanes) per edge, float4 loads. Logit -> exp (unshifted;
// |att| << 88) -> atomically accumulate denom[d] += ex, hnb[d] += ex*nfeat[s].
__global__ void __launch_bounds__(256) att_fused_kernel(const float* __restrict__ efeat,
                                                        const float* __restrict__ nfeat,
                                                        const int* __restrict__ src,
                                                        const int* __restrict__ dst,
                                                        const int* __restrict__ etype,
                                                        float* __restrict__ hnb) {
    int gt = blockIdx.x * blockDim.x + threadIdx.x;
    int e  = gt >> 4;                 // 16 lanes per edge
    int sl = threadIdx.x & 15;
    if (e >= N_EDGES) return;

    int s = src[e], d = dst[e], r = etype[e];
    const float4* t4 = (const float4*)(g_proj + ((size_t)r * N_NODES + s) * DIM);
    const float4* h4 = (const float4*)(g_proj + ((size_t)r * N_NODES + d) * DIM);
    const float4* e4 = (const float4*)(efeat + (size_t)e * DIM);

    float4 tv = t4[sl], hv = h4[sl];
    float4 ev = __ldcs(&e4[sl]);      // streaming: keep L2 for proj rows

    float val = tv.x * fast_tanh(hv.x + ev.x)
              + tv.y * fast_tanh(hv.y + ev.y)
              + tv.z * fast_tanh(hv.z + ev.z)
              + tv.w * fast_tanh(hv.w + ev.w);

    #pragma unroll
    for (int off = 8; off; off >>= 1) val += __shfl_xor_sync(0xffffffffu, val, off);

    float ex = __expf(val);           // in all 16 lanes of the half-warp

    if (sl == 0) atomicAdd(&g_denom[d], ex);
    {
        float4 v = ((const float4*)(nfeat + (size_t)s * DIM))[sl];
        float4 w = make_float4(ex * v.x, ex * v.y, ex * v.z, ex * v.w);
        atomicAdd(((float4*)(hnb + (size_t)d * DIM)) + sl, w);
    }
}

// ---------------- launch #6: normalize hnb by denom ----------------
__global__ void normalize_kernel(float* __restrict__ hnb) {
    int i = blockIdx.x * blockDim.x + threadIdx.x;   // float4 index
    if (i >= N_NODES * DIM / 4) return;
    int n = i >> 4;
    float den = g_denom[n];
    float inv = (den > 0.f) ? (1.f / den) : 0.f;     // empty segment -> 0
    float4 v = ((float4*)hnb)[i];
    ((float4*)hnb)[i] = make_float4(v.x * inv, v.y * inv, v.z * inv, v.w * inv);
}

// ---------------- launches #7/#8: out (+)= leaky((nfeat OP hnb) @ W) -------
template <int MODE>
__global__ void __launch_bounds__(128) out_gemm_kernel(const float* __restrict__ nfeat,
                                                       const float* __restrict__ hnb,
                                                       const float* __restrict__ W,
                                                       float* __restrict__ out,
                                                       int accumulate) {
    __shared__ __align__(16) float Ws[64 * 64];
    __shared__ __align__(16) float Ss[64 * 64];

    const int n0  = blockIdx.x * 64;
    const int tid = threadIdx.x;

    {
        const float4* wsrc = (const float4*)W;
        float4* wdst = (float4*)Ws;
        #pragma unroll
        for (int i = tid; i < 1024; i += 128) wdst[i] = wsrc[i];
    }
    {
        int nn = tid & 63;
        int n  = n0 + nn;
        if (n < N_NODES) {
            const float4* a4 = (const float4*)(nfeat + (size_t)n * DIM);
            const float4* b4 = (const float4*)(hnb  + (size_t)n * DIM);
            for (int c4 = (tid >> 6); c4 < 16; c4 += 2) {
                float4 a = a4[c4], b = b4[c4];
                float4 sv;
                if (MODE == 0) sv = make_float4(a.x + b.x, a.y + b.y, a.z + b.z, a.w + b.w);
                else           sv = make_float4(a.x * b.x, a.y * b.y, a.z * b.z, a.w * b.w);
                Ss[(c4 * 4 + 0) * 64 + nn] = sv.x;
                Ss[(c4 * 4 + 1) * 64 + nn] = sv.y;
                Ss[(c4 * 4 + 2) * 64 + nn] = sv.z;
                Ss[(c4 * 4 + 3) * 64 + nn] = sv.w;
            }
        } else {
            for (int c4 = (tid >> 6); c4 < 16; c4 += 2) {
                Ss[(c4 * 4 + 0) * 64 + nn] = 0.f;
                Ss[(c4 * 4 + 1) * 64 + nn] = 0.f;
                Ss[(c4 * 4 + 2) * 64 + nn] = 0.f;
                Ss[(c4 * 4 + 3) * 64 + nn] = 0.f;
            }
        }
    }
    __syncthreads();

    const int cg = tid & 3;
    const int tr = tid >> 2;

    unsigned long long acc[2][8];
    #pragma unroll
    for (int m = 0; m < 2; m++)
        #pragma unroll
        for (int j = 0; j < 8; j++) acc[m][j] = 0ull;

    #pragma unroll 8
    for (int d = 0; d < 64; d++) {
        unsigned long long w2[8];
        const float* wrow = Ws + d * 64 + cg * 16;
        #pragma unroll
        for (int j = 0; j < 8; j++)
            w2[j] = *(const unsigned long long*)(wrow + 2 * j);
        #pragma unroll
        for (int m = 0; m < 2; m++) {
            unsigned long long x2 = pack2(Ss[d * 64 + tr * 2 + m]);
            #pragma unroll
            for (int j = 0; j < 8; j++) ffma2(acc[m][j], x2, w2[j]);
        }
    }

    #pragma unroll
    for (int m = 0; m < 2; m++) {
        int n = n0 + tr * 2 + m;
        if (n >= N_NODES) continue;
        float* orow = out + (size_t)n * DIM + cg * 16;
        #pragma unroll
        for (int j = 0; j < 8; j++) {
            float lo, hi;
            unpack2(acc[m][j], lo, hi);
            lo = leaky(lo);
            hi = leaky(hi);
            if (accumulate) { orow[2 * j] += lo; orow[2 * j + 1] += hi; }
            else            { orow[2 * j]  = lo; orow[2 * j + 1]  = hi; }
        }
    }
}

// ---------------- launch ----------------
extern "C" void kernel_launch(void* const* d_in, const int* in_sizes, int n_in,
                              void* d_out, int out_size) {
    const float* nfeat = (const float*)d_in[0];
    const float* efeat = (const float*)d_in[1];
    const float* relW  = (const float*)d_in[2];
    const float* W1    = (const float*)d_in[3];
    const float* W2    = (const float*)d_in[4];
    const int*   src   = (const int*)d_in[5];
    const int*   dst   = (const int*)d_in[6];
    const int*   etype = (const int*)d_in[7];

    float* hnb  = (float*)d_out;
    float* out2 = (float*)d_out + (size_t)N_NODES * DIM;

    // #1, #2
    init_hnb_kernel<<<(N_NODES * DIM / 4 + 255) / 256, 256>>>(hnb);
    init_denom_kernel<<<(N_NODES + 255) / 256, 256>>>();
    // #3, #4  <- ncu profiles #4 (proj second half)
    dim3 g1((N_NODES + PROJ_TN - 1) / PROJ_TN, N_REL / 2);
    proj_kernel<<<g1, 128>>>(nfeat, relW, 0);
    proj_kernel<<<g1, 128>>>(nfeat, relW, 8);
    // #5
    att_fused_kernel<<<(N_EDGES * 16 + 255) / 256, 256>>>(efeat, nfeat, src, dst, etype, hnb);
    // #6
    normalize_kernel<<<(N_NODES * DIM / 4 + 255) / 256, 256>>>(hnb);
    // #7, #8
    out_gemm_kernel<0><<<(N_NODES + 63) / 64, 128>>>(nfeat, hnb, W1, out2, 0);
    out_gemm_kernel<1><<<(N_NODES + 63) / 64, 128>>>(nfeat, hnb, W2, out2, 1);
}